// round 16
// baseline (speedup 1.0000x reference)
#include <cuda_runtime.h>
#include <math.h>

// x: [64, 3, 512, 512] fp32 -> out [192, 6]: per 8x8 block |FFT2| at bins
// (0,1),(1,0),(1,1),(2,2),(3,3),(4,4), mean over 64x64 blocks per plane.
//
// R15 = R10 (record: 31.2us wall, ~6.6TB/s; L2 line-prefetch ONE iteration /
// +128KB ahead -- depth/shape/descriptor variants all proven flat) plus one
// delta: a prologue line-prefetch burst of each thread's iteration-0 tile.
// Iteration 0 (24MB chip-wide, 12% of traffic) was the only demand-miss-cold
// region; the prologue burst gives DRAM the smooth bulk order from cycle 0,
// demand loads merge into in-flight MSHRs.

#define PLANE_ELEMS (512 * 512)
#define NBLOCKS_PER_PLANE 4096   // 64 x 64 blocks of 8x8
#define THREADS 512
#define KITERS (NBLOCKS_PER_PLANE / THREADS)   // 8

__global__ __launch_bounds__(THREADS, 2)
void dct_bands_kernel(const float* __restrict__ x, float* __restrict__ out) {
    const int plane = blockIdx.x;                       // b*3 + c, 0..191
    const float* __restrict__ base = x + (size_t)plane * PLANE_ELEMS;
    const int tid  = threadIdx.x;
    const int lane = tid & 31;

    constexpr float S = 0.70710678118654752440f;
    // Twiddle tables: e^{-i * m * theta}; unrolled loop -> folded to immediates.
    const float C45[8]  = {1.f,  S, 0.f, -S, -1.f, -S, 0.f,  S};
    const float S45[8]  = {0.f,  S, 1.f,  S,  0.f, -S, -1.f, -S};
    const float C90[8]  = {1.f, 0.f, -1.f, 0.f, 1.f, 0.f, -1.f, 0.f};
    const float S90[8]  = {0.f, 1.f, 0.f, -1.f, 0.f, 1.f, 0.f, -1.f};
    const float C135[8] = {1.f, -S, 0.f,  S, -1.f,  S, 0.f, -S};
    const float S135[8] = {0.f,  S, -1.f, S,  0.f, -S, 1.f, -S};

    // Prologue: bulk-order line prefetch of this thread's iteration-0 tile.
    // Demands that follow merge into the in-flight requests; DRAM sees the
    // smooth sequenced pattern from the first byte.
    {
        const int gi0 = tid >> 6, gj0 = tid & 63;
        const float* p0 = base + ((size_t)(gi0 << 3) << 9) + (gj0 << 3);
        if ((lane & 3) == 0) {
            #pragma unroll
            for (int m = 0; m < 8; ++m)
                asm volatile("prefetch.global.L2 [%0];" :: "l"(p0 + m * 512));
        }
    }

    float sum0 = 0.f, sum1 = 0.f, sum2 = 0.f, sum3 = 0.f, sum4 = 0.f, sum5 = 0.f;

    #pragma unroll 1
    for (int k = 0; k < KITERS; ++k) {
        const int bl = tid + (k << 9);            // block index within plane
        const int gi = bl >> 6;                   // block row (0..63)
        const int gj = bl & 63;                   // block col (0..63)
        const float* bp = base + ((size_t)(gi << 3) << 9) + (gj << 3);

        // Prefetch next tile's 8 rows into L2 (thread's k+1 tile sits
        // +8 block-rows = +32768 floats = 128KB ahead). One prefetch per
        // 128B line: lanes 0,4,...,28 cover the warp's 8 lines per row.
        if (k + 1 < KITERS && (lane & 3) == 0) {
            const float* pn = bp + 32768;
            #pragma unroll
            for (int m = 0; m < 8; ++m)
                asm volatile("prefetch.global.L2 [%0];" :: "l"(pn + m * 512));
        }

        float a01r = 0.f, a01i = 0.f;
        float a10r = 0.f, a10i = 0.f;
        float a11r = 0.f, a11i = 0.f;
        float a22r = 0.f, a22i = 0.f;
        float a33r = 0.f, a33i = 0.f;
        float a44  = 0.f;

        #pragma unroll
        for (int m = 0; m < 8; ++m) {
            const float4 lo = __ldcs(reinterpret_cast<const float4*>(bp + m * 512));
            const float4 hi = __ldcs(reinterpret_cast<const float4*>(bp + m * 512 + 4));
            const float x0 = lo.x, x1 = lo.y, x2 = lo.z, x3 = lo.w;
            const float x4 = hi.x, x5 = hi.y, x6 = hi.z, x7 = hi.w;

            const float p  = x1 - x3 - x5 + x7;
            const float q  = x1 + x3 - x5 - x7;
            const float e0 = x0 - x4;
            const float e2 = x2 - x6;

            const float r0  = x0 + x1 + x2 + x3 + x4 + x5 + x6 + x7;
            const float re1 = e0 + p * S;
            const float im1 = -(q * S + e2);
            const float re2 = x0 - x2 + x4 - x6;
            const float im2 = -(x1 - x3 + x5 - x7);
            const float re3 = e0 - p * S;
            const float im3 = -(q * S - e2);
            const float r4  = x0 - x1 + x2 - x3 + x4 - x5 + x6 - x7;

            const float w1r = C45[m],  w1i = -S45[m];
            const float w2r = C90[m],  w2i = -S90[m];
            const float w3r = C135[m], w3i = -S135[m];

            a01r += re1;                  a01i += im1;
            a10r += r0 * w1r;             a10i += r0 * w1i;
            a11r += re1 * w1r - im1 * w1i;
            a11i += re1 * w1i + im1 * w1r;
            a22r += re2 * w2r - im2 * w2i;
            a22i += re2 * w2i + im2 * w2r;
            a33r += re3 * w3r - im3 * w3i;
            a33i += re3 * w3i + im3 * w3r;
            a44  += (m & 1) ? -r4 : r4;
        }

        sum0 += sqrtf(a01r * a01r + a01i * a01i);
        sum1 += sqrtf(a10r * a10r + a10i * a10i);
        sum2 += sqrtf(a11r * a11r + a11i * a11i);
        sum3 += sqrtf(a22r * a22r + a22i * a22i);
        sum4 += sqrtf(a33r * a33r + a33i * a33i);
        sum5 += fabsf(a44);
    }

    // ---- CTA reduction: 512 threads x 6 floats -> out[plane*6 + band] ----
    float v[6] = {sum0, sum1, sum2, sum3, sum4, sum5};

    #pragma unroll
    for (int j = 0; j < 6; ++j) {
        #pragma unroll
        for (int o = 16; o > 0; o >>= 1)
            v[j] += __shfl_down_sync(0xffffffffu, v[j], o);
    }

    __shared__ float red[16][6];
    const int warp = tid >> 5;
    if (lane == 0) {
        #pragma unroll
        for (int j = 0; j < 6; ++j) red[warp][j] = v[j];
    }
    __syncthreads();

    if (tid < 6) {
        float t = 0.f;
        #pragma unroll
        for (int w = 0; w < 16; ++w) t += red[w][tid];
        out[plane * 6 + tid] = t * (1.0f / (float)NBLOCKS_PER_PLANE);
    }
}

extern "C" void kernel_launch(void* const* d_in, const int* in_sizes, int n_in,
                              void* d_out, int out_size) {
    const float* x = (const float*)d_in[0];
    float* out = (float*)d_out;
    const int n_planes = in_sizes[0] / PLANE_ELEMS;   // 64*3 = 192
    dct_bands_kernel<<<n_planes, THREADS>>>(x, out);
}

// round 17
// speedup vs baseline: 1.0082x; 1.0082x over previous
#include <cuda_runtime.h>
#include <math.h>

// x: [64, 3, 512, 512] fp32 -> out [192, 6]: per 8x8 block |FFT2| at bins
// (0,1),(1,0),(1,1),(2,2),(3,3),(4,4), mean over 64x64 blocks per plane.
//
// R16 = exact R10 record kernel (31.2us wall, ~6.6TB/s): R0 streaming loop +
// L2 line-prefetch of the next tile (ONE iteration / +128KB ahead, lanes
// 0,4,...,28, one per 128B line). All prefetch-axis variants (deeper,
// interleaved, bulk-descriptor, cold-start prologue) measured flat or worse;
// each added-instruction rider cost ~+0.25us. This is the optimum found.

#define PLANE_ELEMS (512 * 512)
#define NBLOCKS_PER_PLANE 4096   // 64 x 64 blocks of 8x8
#define THREADS 512
#define KITERS (NBLOCKS_PER_PLANE / THREADS)   // 8

__global__ __launch_bounds__(THREADS, 2)
void dct_bands_kernel(const float* __restrict__ x, float* __restrict__ out) {
    const int plane = blockIdx.x;                       // b*3 + c, 0..191
    const float* __restrict__ base = x + (size_t)plane * PLANE_ELEMS;
    const int tid  = threadIdx.x;
    const int lane = tid & 31;

    constexpr float S = 0.70710678118654752440f;
    // Twiddle tables: e^{-i * m * theta}; unrolled loop -> folded to immediates.
    const float C45[8]  = {1.f,  S, 0.f, -S, -1.f, -S, 0.f,  S};
    const float S45[8]  = {0.f,  S, 1.f,  S,  0.f, -S, -1.f, -S};
    const float C90[8]  = {1.f, 0.f, -1.f, 0.f, 1.f, 0.f, -1.f, 0.f};
    const float S90[8]  = {0.f, 1.f, 0.f, -1.f, 0.f, 1.f, 0.f, -1.f};
    const float C135[8] = {1.f, -S, 0.f,  S, -1.f,  S, 0.f, -S};
    const float S135[8] = {0.f,  S, -1.f, S,  0.f, -S, 1.f, -S};

    float sum0 = 0.f, sum1 = 0.f, sum2 = 0.f, sum3 = 0.f, sum4 = 0.f, sum5 = 0.f;

    #pragma unroll 1
    for (int k = 0; k < KITERS; ++k) {
        const int bl = tid + (k << 9);            // block index within plane
        const int gi = bl >> 6;                   // block row (0..63)
        const int gj = bl & 63;                   // block col (0..63)
        const float* bp = base + ((size_t)(gi << 3) << 9) + (gj << 3);

        // Prefetch next tile's 8 rows into L2 (thread's k+1 tile sits
        // +8 block-rows = +32768 floats = 128KB ahead). One prefetch per
        // 128B line: lanes 0,4,...,28 cover the warp's 8 lines per row.
        if (k + 1 < KITERS && (lane & 3) == 0) {
            const float* pn = bp + 32768;
            #pragma unroll
            for (int m = 0; m < 8; ++m)
                asm volatile("prefetch.global.L2 [%0];" :: "l"(pn + m * 512));
        }

        float a01r = 0.f, a01i = 0.f;
        float a10r = 0.f, a10i = 0.f;
        float a11r = 0.f, a11i = 0.f;
        float a22r = 0.f, a22i = 0.f;
        float a33r = 0.f, a33i = 0.f;
        float a44  = 0.f;

        #pragma unroll
        for (int m = 0; m < 8; ++m) {
            const float4 lo = __ldcs(reinterpret_cast<const float4*>(bp + m * 512));
            const float4 hi = __ldcs(reinterpret_cast<const float4*>(bp + m * 512 + 4));
            const float x0 = lo.x, x1 = lo.y, x2 = lo.z, x3 = lo.w;
            const float x4 = hi.x, x5 = hi.y, x6 = hi.z, x7 = hi.w;

            const float p  = x1 - x3 - x5 + x7;
            const float q  = x1 + x3 - x5 - x7;
            const float e0 = x0 - x4;
            const float e2 = x2 - x6;

            const float r0  = x0 + x1 + x2 + x3 + x4 + x5 + x6 + x7;
            const float re1 = e0 + p * S;
            const float im1 = -(q * S + e2);
            const float re2 = x0 - x2 + x4 - x6;
            const float im2 = -(x1 - x3 + x5 - x7);
            const float re3 = e0 - p * S;
            const float im3 = -(q * S - e2);
            const float r4  = x0 - x1 + x2 - x3 + x4 - x5 + x6 - x7;

            const float w1r = C45[m],  w1i = -S45[m];
            const float w2r = C90[m],  w2i = -S90[m];
            const float w3r = C135[m], w3i = -S135[m];

            a01r += re1;                  a01i += im1;
            a10r += r0 * w1r;             a10i += r0 * w1i;
            a11r += re1 * w1r - im1 * w1i;
            a11i += re1 * w1i + im1 * w1r;
            a22r += re2 * w2r - im2 * w2i;
            a22i += re2 * w2i + im2 * w2r;
            a33r += re3 * w3r - im3 * w3i;
            a33i += re3 * w3i + im3 * w3r;
            a44  += (m & 1) ? -r4 : r4;
        }

        sum0 += sqrtf(a01r * a01r + a01i * a01i);
        sum1 += sqrtf(a10r * a10r + a10i * a10i);
        sum2 += sqrtf(a11r * a11r + a11i * a11i);
        sum3 += sqrtf(a22r * a22r + a22i * a22i);
        sum4 += sqrtf(a33r * a33r + a33i * a33i);
        sum5 += fabsf(a44);
    }

    // ---- CTA reduction: 512 threads x 6 floats -> out[plane*6 + band] ----
    float v[6] = {sum0, sum1, sum2, sum3, sum4, sum5};

    #pragma unroll
    for (int j = 0; j < 6; ++j) {
        #pragma unroll
        for (int o = 16; o > 0; o >>= 1)
            v[j] += __shfl_down_sync(0xffffffffu, v[j], o);
    }

    __shared__ float red[16][6];
    const int warp = tid >> 5;
    if (lane == 0) {
        #pragma unroll
        for (int j = 0; j < 6; ++j) red[warp][j] = v[j];
    }
    __syncthreads();

    if (tid < 6) {
        float t = 0.f;
        #pragma unroll
        for (int w = 0; w < 16; ++w) t += red[w][tid];
        out[plane * 6 + tid] = t * (1.0f / (float)NBLOCKS_PER_PLANE);
    }
}

extern "C" void kernel_launch(void* const* d_in, const int* in_sizes, int n_in,
                              void* d_out, int out_size) {
    const float* x = (const float*)d_in[0];
    float* out = (float*)d_out;
    const int n_planes = in_sizes[0] / PLANE_ELEMS;   // 64*3 = 192
    dct_bands_kernel<<<n_planes, THREADS>>>(x, out);
}